// round 7
// baseline (speedup 1.0000x reference)
#include <cuda_runtime.h>
#include <cstdint>

// key = ((x*64+y)*64+z)*64+b  in [0, 2^24)
constexpr int KEYSPACE     = 1 << 24;
constexpr int WORDS        = KEYSPACE / 32;                 // 524288
constexpr int SCAN_THREADS = 256;                           // 4 words/thread
constexpr int SCAN_TILES   = WORDS / (4 * SCAN_THREADS);    // 512
constexpr int EP_BLOCKS    = 512;                           // extras+pad kernel
constexpr unsigned KEYMASK   = 0x00FFFFFFu;
constexpr unsigned EXTRA_BIT = 0x80000000u;

__device__ unsigned g_bitmap[WORDS];             // presence bits (self-cleaned by scan)
__device__ uint2    g_tab[WORDS];                // {bits, rank}
__device__ unsigned g_key[1 << 20];              // per-point key | EXTRA_BIT
__device__ unsigned g_extra[1 << 20];            // indices of non-owner duplicate points
__device__ unsigned long long g_desc[SCAN_TILES];// lookback descriptors (reset by extras_pad)
__device__ unsigned g_extra_cnt;                 // reset by extras_pad
__device__ unsigned g_done;                      // extras_pad completion counter
__device__ unsigned g_total;                     // unique voxel count

// ---------------------------------------------------------------------------
__device__ __forceinline__ unsigned make_key(int4 c) {
    return ((unsigned)((c.x * 64 + c.y) * 64 + c.z)) * 64u + (unsigned)c.w;
}

// Claim voxels, 2 points per thread for atomic MLP. First claimant = owner;
// later points are appended to the extras list and flagged in the stored key.
__global__ void k_setbits(const int4* __restrict__ coords, int n) {
    int i = (blockIdx.x * blockDim.x + threadIdx.x) * 2;
    if (i >= n) return;
    int4 c0 = __ldg(&coords[i]);
    unsigned k0 = make_key(c0);
    unsigned k1 = 0xFFFFFFFFu;
    if (i + 1 < n) k1 = make_key(__ldg(&coords[i + 1]));

    unsigned old0 = atomicOr(&g_bitmap[k0 >> 5], 1u << (k0 & 31));
    unsigned old1 = 0;
    if (k1 != 0xFFFFFFFFu)
        old1 = atomicOr(&g_bitmap[k1 >> 5], 1u << (k1 & 31));

    if (old0 & (1u << (k0 & 31))) {
        k0 |= EXTRA_BIT;
        g_extra[atomicAdd(&g_extra_cnt, 1u)] = (unsigned)i;
    }
    if (k1 != 0xFFFFFFFFu && (old1 & (1u << (k1 & 31)))) {
        k1 |= EXTRA_BIT;
        g_extra[atomicAdd(&g_extra_cnt, 1u)] = (unsigned)(i + 1);
    }
    if (i + 1 < n) {
        uint2 pk = make_uint2(k0, k1);
        *reinterpret_cast<uint2*>(&g_key[i]) = pk;
    } else {
        g_key[i] = k0;
    }
}

// ---------------------------------------------------------------------------
__device__ __forceinline__ unsigned long long ld_relaxed(const unsigned long long* p) {
    unsigned long long v;
    asm volatile("ld.relaxed.gpu.global.u64 %0, [%1];" : "=l"(v) : "l"(p) : "memory");
    return v;
}

__device__ __forceinline__ unsigned block_excl_scan(unsigned v, unsigned* sh) {
    unsigned lane = threadIdx.x & 31;
    unsigned wid  = threadIdx.x >> 5;
    unsigned x = v;
    #pragma unroll
    for (int o = 1; o < 32; o <<= 1) {
        unsigned y = __shfl_up_sync(0xFFFFFFFFu, x, o);
        if (lane >= o) x += y;
    }
    if (lane == 31) sh[wid] = x;
    __syncthreads();
    if (wid == 0) {
        unsigned nw = blockDim.x >> 5;
        unsigned w2 = (lane < nw) ? sh[lane] : 0u;
        #pragma unroll
        for (int o = 1; o < 32; o <<= 1) {
            unsigned y = __shfl_up_sync(0xFFFFFFFFu, w2, o);
            if (lane >= o) w2 += y;
        }
        if (lane < nw) sh[lane] = w2;
    }
    __syncthreads();
    unsigned warp_prefix = (wid > 0) ? sh[wid - 1] : 0u;
    return warp_prefix + x - v;   // exclusive
}

// Single-pass prefix-popcount, warp-parallel decoupled lookback.
// All 512 tiles are co-resident, so blockIdx ordering cannot deadlock.
__global__ void k_scan() {
    __shared__ unsigned sh[32];
    __shared__ unsigned sh_total, sh_prefix;
    unsigned tile = blockIdx.x;
    unsigned t = tile * SCAN_THREADS + threadIdx.x;       // uint4 index
    uint4 w = reinterpret_cast<const uint4*>(g_bitmap)[t];
    reinterpret_cast<uint4*>(g_bitmap)[t] = make_uint4(0u, 0u, 0u, 0u); // self-clean
    unsigned p0 = __popc(w.x), p1 = __popc(w.y), p2 = __popc(w.z), p3 = __popc(w.w);
    unsigned sum  = p0 + p1 + p2 + p3;
    unsigned excl = block_excl_scan(sum, sh);
    if (threadIdx.x == SCAN_THREADS - 1) sh_total = excl + sum;
    __syncthreads();
    unsigned T = sh_total;

    if (threadIdx.x < 32) {
        unsigned lane = threadIdx.x;
        unsigned prefix = 0;
        if (tile == 0) {
            if (lane == 0) {
                atomicExch(&g_desc[0], (2ull << 32) | (unsigned long long)T);
                sh_prefix = 0u;
            }
        } else {
            if (lane == 0)
                atomicExch(&g_desc[tile], (1ull << 32) | (unsigned long long)T);
            int base = (int)tile - 1;
            while (true) {
                int j = base - (int)lane;
                unsigned long long d = (j >= 0) ? ld_relaxed(&g_desc[j]) : (2ull << 32);
                unsigned st = (unsigned)(d >> 32);
                unsigned m2 = __ballot_sync(0xFFFFFFFFu, st == 2u);
                unsigned m0 = __ballot_sync(0xFFFFFFFFu, st == 0u);
                int c2 = m2 ? (__ffs(m2) - 1) : 32;
                int c0 = m0 ? (__ffs(m0) - 1) : 32;
                if (c0 < c2) continue;                 // nearest pred not ready: retry
                if (c2 < 32) {                         // prefix closed within window
                    unsigned val = (lane <= (unsigned)c2) ? (unsigned)d : 0u;
                    prefix += __reduce_add_sync(0xFFFFFFFFu, val);
                    break;
                }
                prefix += __reduce_add_sync(0xFFFFFFFFu, (unsigned)d);
                base -= 32;
            }
            if (lane == 0) {
                atomicExch(&g_desc[tile],
                           (2ull << 32) | (unsigned long long)(prefix + T));
                sh_prefix = prefix;
                if (tile == SCAN_TILES - 1) g_total = prefix + T;
            }
        }
    }
    __syncthreads();

    unsigned base = sh_prefix + excl;
    uint4* tp = reinterpret_cast<uint4*>(g_tab + (size_t)t * 4);
    tp[0] = make_uint4(w.x, base,           w.y, base + p0);
    tp[1] = make_uint4(w.z, base + p0 + p1, w.w, base + p0 + p1 + p2);
}

// ---------------------------------------------------------------------------
// Scatter: owners only, pure streaming stores. Stage 1 computes rank once per
// point; stage 2 writes 128B rows with 8-lane teams, feat reads coalesced.
__global__ void k_scatter(const float4* __restrict__ feat,
                          float* __restrict__ out, int n) {
    __shared__ unsigned s_rd[256];
    int base = blockIdx.x * 256;
    int p = base + threadIdx.x;
    unsigned rd = 0xFFFFFFFFu;
    if (p < n) {
        unsigned k = __ldcs(&g_key[p]);
        if (!(k & EXTRA_BIT)) {
            unsigned w = k >> 5, b = k & 31;
            uint2 e = __ldg(&g_tab[w]);               // {bits, rank}
            rd = e.y + __popc(e.x & ((1u << b) - 1u));
        }
    }
    s_rd[threadIdx.x] = rd;
    __syncthreads();
    int team = threadIdx.x >> 3;
    int lane = threadIdx.x & 7;
    #pragma unroll
    for (int j = 0; j < 8; j++) {
        int pl = j * 32 + team;
        int pg = base + pl;
        if (pg < n) {
            unsigned r = s_rd[pl];
            if (r != 0xFFFFFFFFu) {
                float4 v = __ldcs(&feat[(size_t)pg * 8 + lane]);
                float* dst = out + (size_t)r * 32 + lane * 4;
                asm volatile("st.global.cs.v4.f32 [%0], {%1,%2,%3,%4};"
                             :: "l"(dst), "f"(v.x), "f"(v.y), "f"(v.z), "f"(v.w)
                             : "memory");
            }
        }
    }
}

// ---------------------------------------------------------------------------
// Extras (red.add onto owner-written rows) + zero padding rows [g_total, N).
// Last block to finish resets scan/setbits state for the next graph replay.
__global__ void k_extras_pad(const float4* __restrict__ feat,
                             float* __restrict__ out, int n) {
    unsigned extra_cnt = g_extra_cnt;                     // read before any reset
    if (blockIdx.x < EP_BLOCKS / 2) {
        unsigned tot = extra_cnt * 8u;
        unsigned stride = (EP_BLOCKS / 2) * 256;
        for (unsigned i = blockIdx.x * 256 + threadIdx.x; i < tot; i += stride) {
            unsigned p = g_extra[i >> 3];
            int lane = i & 7;
            unsigned k = g_key[p] & KEYMASK;
            unsigned w = k >> 5, b = k & 31;
            uint2 e = __ldg(&g_tab[w]);
            unsigned r = e.y + __popc(e.x & ((1u << b) - 1u));
            float4 v = __ldg(&feat[(size_t)p * 8 + lane]);
            float* dst = out + (size_t)r * 32 + lane * 4;
            asm volatile("red.global.add.v4.f32 [%0], {%1,%2,%3,%4};"
                         :: "l"(dst), "f"(v.x), "f"(v.y), "f"(v.z), "f"(v.w)
                         : "memory");
        }
    } else {
        float4 z = make_float4(0.f, 0.f, 0.f, 0.f);
        size_t start  = (size_t)g_total * 8;
        size_t end    = (size_t)n * 8;
        size_t stride = (size_t)(EP_BLOCKS / 2) * 256;
        for (size_t i = start + (size_t)(blockIdx.x - EP_BLOCKS / 2) * 256 + threadIdx.x;
             i < end; i += stride)
            reinterpret_cast<float4*>(out)[i] = z;
    }
    // ---- last-finishing block resets pipeline state for the next call ----
    __syncthreads();
    __shared__ unsigned s_last;
    if (threadIdx.x == 0) {
        __threadfence();
        s_last = (atomicAdd(&g_done, 1u) == (unsigned)(gridDim.x - 1));
    }
    __syncthreads();
    if (s_last) {
        if (threadIdx.x < SCAN_TILES / 2) {       // 256 threads x 2 descriptors
            g_desc[threadIdx.x * 2]     = 0ull;
            g_desc[threadIdx.x * 2 + 1] = 0ull;
        }
        if (threadIdx.x == 0) { g_extra_cnt = 0u; g_done = 0u; }
    }
}

// ---------------------------------------------------------------------------
extern "C" void kernel_launch(void* const* d_in, const int* in_sizes, int n_in,
                              void* d_out, int out_size) {
    const int4*   coords = (const int4*)d_in[0];    // [N,4] int32
    const float4* feat   = (const float4*)d_in[1];  // [N,32] f32
    float* out = (float*)d_out;
    int n = in_sizes[0] / 4;

    k_setbits   <<<(n / 2 + 255) / 256, 256>>>(coords, n);
    k_scan      <<<SCAN_TILES, SCAN_THREADS>>>();
    k_scatter   <<<(n + 255) / 256, 256>>>(feat, out, n);
    k_extras_pad<<<EP_BLOCKS, 256>>>(feat, out, n);
}

// round 8
// speedup vs baseline: 1.0259x; 1.0259x over previous
#include <cuda_runtime.h>
#include <cstdint>

// key = ((x*64+y)*64+z)*64+b  in [0, 2^24)
constexpr int KEYSPACE     = 1 << 24;
constexpr int WORDS        = KEYSPACE / 32;                 // 524288
constexpr int SCAN_THREADS = 256;                           // 4 words/thread
constexpr int SCAN_TILES   = WORDS / (4 * SCAN_THREADS);    // 512
constexpr int PAD_BLOCKS   = 128;    // pad-zero blocks appended to scatter grid
constexpr int EXR_BLOCKS   = 32;     // extras-rank blocks appended to scatter grid
constexpr int EX_BLOCKS    = 1024;   // extras red kernel
constexpr unsigned KEYMASK   = 0x00FFFFFFu;
constexpr unsigned EXTRA_BIT = 0x80000000u;

__device__ unsigned g_bitmap[WORDS];             // presence bits (self-cleaned by scan)
__device__ uint2    g_tab[WORDS];                // {bits, rank}
__device__ unsigned g_key[1 << 20];              // per-point key | EXTRA_BIT
__device__ unsigned g_extra[1 << 20];            // point indices of non-owner duplicates
__device__ unsigned g_extra_rank[1 << 20];       // their output ranks (precomputed)
__device__ unsigned long long g_desc[SCAN_TILES];// lookback descriptors (reset below)
__device__ unsigned g_extra_cnt;                 // reset by extras kernel
__device__ unsigned g_done;                      // completion counter
__device__ unsigned g_total;                     // unique voxel count

// ---------------------------------------------------------------------------
__device__ __forceinline__ unsigned make_key(int4 c) {
    return ((unsigned)((c.x * 64 + c.y) * 64 + c.z)) * 64u + (unsigned)c.w;
}

// Claim voxels, 2 points per thread for atomic MLP. First claimant = owner;
// later points are appended to the extras list and flagged in the stored key.
__global__ void k_setbits(const int4* __restrict__ coords, int n) {
    int i = (blockIdx.x * blockDim.x + threadIdx.x) * 2;
    if (i >= n) return;
    unsigned k0 = make_key(__ldg(&coords[i]));
    unsigned k1 = 0xFFFFFFFFu;
    if (i + 1 < n) k1 = make_key(__ldg(&coords[i + 1]));

    unsigned old0 = atomicOr(&g_bitmap[k0 >> 5], 1u << (k0 & 31));
    unsigned old1 = 0;
    if (k1 != 0xFFFFFFFFu)
        old1 = atomicOr(&g_bitmap[k1 >> 5], 1u << (k1 & 31));

    if (old0 & (1u << (k0 & 31))) {
        k0 |= EXTRA_BIT;
        g_extra[atomicAdd(&g_extra_cnt, 1u)] = (unsigned)i;
    }
    if (k1 != 0xFFFFFFFFu && (old1 & (1u << (k1 & 31)))) {
        k1 |= EXTRA_BIT;
        g_extra[atomicAdd(&g_extra_cnt, 1u)] = (unsigned)(i + 1);
    }
    if (i + 1 < n) {
        *reinterpret_cast<uint2*>(&g_key[i]) = make_uint2(k0, k1);
    } else {
        g_key[i] = k0;
    }
}

// ---------------------------------------------------------------------------
__device__ __forceinline__ unsigned long long ld_relaxed(const unsigned long long* p) {
    unsigned long long v;
    asm volatile("ld.relaxed.gpu.global.u64 %0, [%1];" : "=l"(v) : "l"(p) : "memory");
    return v;
}

__device__ __forceinline__ unsigned block_excl_scan(unsigned v, unsigned* sh) {
    unsigned lane = threadIdx.x & 31;
    unsigned wid  = threadIdx.x >> 5;
    unsigned x = v;
    #pragma unroll
    for (int o = 1; o < 32; o <<= 1) {
        unsigned y = __shfl_up_sync(0xFFFFFFFFu, x, o);
        if (lane >= o) x += y;
    }
    if (lane == 31) sh[wid] = x;
    __syncthreads();
    if (wid == 0) {
        unsigned nw = blockDim.x >> 5;
        unsigned w2 = (lane < nw) ? sh[lane] : 0u;
        #pragma unroll
        for (int o = 1; o < 32; o <<= 1) {
            unsigned y = __shfl_up_sync(0xFFFFFFFFu, w2, o);
            if (lane >= o) w2 += y;
        }
        if (lane < nw) sh[lane] = w2;
    }
    __syncthreads();
    unsigned warp_prefix = (wid > 0) ? sh[wid - 1] : 0u;
    return warp_prefix + x - v;   // exclusive
}

// Single-pass prefix-popcount, warp-parallel decoupled lookback.
__global__ void k_scan() {
    __shared__ unsigned sh[32];
    __shared__ unsigned sh_total, sh_prefix;
    unsigned tile = blockIdx.x;
    unsigned t = tile * SCAN_THREADS + threadIdx.x;       // uint4 index
    uint4 w = reinterpret_cast<const uint4*>(g_bitmap)[t];
    reinterpret_cast<uint4*>(g_bitmap)[t] = make_uint4(0u, 0u, 0u, 0u); // self-clean
    unsigned p0 = __popc(w.x), p1 = __popc(w.y), p2 = __popc(w.z), p3 = __popc(w.w);
    unsigned sum  = p0 + p1 + p2 + p3;
    unsigned excl = block_excl_scan(sum, sh);
    if (threadIdx.x == SCAN_THREADS - 1) sh_total = excl + sum;
    __syncthreads();
    unsigned T = sh_total;

    if (threadIdx.x < 32) {
        unsigned lane = threadIdx.x;
        unsigned prefix = 0;
        if (tile == 0) {
            if (lane == 0) {
                atomicExch(&g_desc[0], (2ull << 32) | (unsigned long long)T);
                sh_prefix = 0u;
            }
        } else {
            if (lane == 0)
                atomicExch(&g_desc[tile], (1ull << 32) | (unsigned long long)T);
            int base = (int)tile - 1;
            while (true) {
                int j = base - (int)lane;
                unsigned long long d = (j >= 0) ? ld_relaxed(&g_desc[j]) : (2ull << 32);
                unsigned st = (unsigned)(d >> 32);
                unsigned m2 = __ballot_sync(0xFFFFFFFFu, st == 2u);
                unsigned m0 = __ballot_sync(0xFFFFFFFFu, st == 0u);
                int c2 = m2 ? (__ffs(m2) - 1) : 32;
                int c0 = m0 ? (__ffs(m0) - 1) : 32;
                if (c0 < c2) continue;                 // nearest pred not ready
                if (c2 < 32) {
                    unsigned val = (lane <= (unsigned)c2) ? (unsigned)d : 0u;
                    prefix += __reduce_add_sync(0xFFFFFFFFu, val);
                    break;
                }
                prefix += __reduce_add_sync(0xFFFFFFFFu, (unsigned)d);
                base -= 32;
            }
            if (lane == 0) {
                atomicExch(&g_desc[tile],
                           (2ull << 32) | (unsigned long long)(prefix + T));
                sh_prefix = prefix;
                if (tile == SCAN_TILES - 1) g_total = prefix + T;
            }
        }
    }
    __syncthreads();

    unsigned base = sh_prefix + excl;
    uint4* tp = reinterpret_cast<uint4*>(g_tab + (size_t)t * 4);
    tp[0] = make_uint4(w.x, base,           w.y, base + p0);
    tp[1] = make_uint4(w.z, base + p0 + p1, w.w, base + p0 + p1 + p2);
}

// ---------------------------------------------------------------------------
// Scatter (owners, streaming stores) + two piggyback block ranges that ride
// inside the DRAM-bound window: pad-row zeroing and extras-rank precompute.
// nb = number of scatter blocks (covers n points).
__global__ void k_scatter(const float4* __restrict__ feat,
                          float* __restrict__ out, int n, int nb) {
    if ((int)blockIdx.x < nb) {
        __shared__ unsigned s_rd[256];
        int base = blockIdx.x * 256;
        int p = base + threadIdx.x;
        unsigned rd = 0xFFFFFFFFu;
        if (p < n) {
            unsigned k = __ldcs(&g_key[p]);
            if (!(k & EXTRA_BIT)) {
                unsigned w = k >> 5, b = k & 31;
                uint2 e = __ldg(&g_tab[w]);           // {bits, rank}
                rd = e.y + __popc(e.x & ((1u << b) - 1u));
            }
        }
        s_rd[threadIdx.x] = rd;
        __syncthreads();
        int team = threadIdx.x >> 3;
        int lane = threadIdx.x & 7;
        #pragma unroll
        for (int j = 0; j < 8; j++) {
            int pl = j * 32 + team;
            int pg = base + pl;
            if (pg < n) {
                unsigned r = s_rd[pl];
                if (r != 0xFFFFFFFFu) {
                    float4 v = __ldcs(&feat[(size_t)pg * 8 + lane]);
                    float* dst = out + (size_t)r * 32 + lane * 4;
                    asm volatile("st.global.cs.v4.f32 [%0], {%1,%2,%3,%4};"
                                 :: "l"(dst), "f"(v.x), "f"(v.y), "f"(v.z), "f"(v.w)
                                 : "memory");
                }
            }
        }
    } else if ((int)blockIdx.x < nb + PAD_BLOCKS) {
        // Zero padding rows [g_total, N).
        float4 z = make_float4(0.f, 0.f, 0.f, 0.f);
        size_t start  = (size_t)g_total * 8;
        size_t end    = (size_t)n * 8;
        size_t stride = (size_t)PAD_BLOCKS * 256;
        for (size_t i = start + (size_t)(blockIdx.x - nb) * 256 + threadIdx.x;
             i < end; i += stride)
            reinterpret_cast<float4*>(out)[i] = z;
    } else {
        // Precompute extras ranks (depends only on g_extra/g_key/g_tab).
        unsigned cnt = g_extra_cnt;
        unsigned stride = EXR_BLOCKS * 256;
        for (unsigned i = (blockIdx.x - nb - PAD_BLOCKS) * 256 + threadIdx.x;
             i < cnt; i += stride) {
            unsigned p = g_extra[i];
            unsigned k = g_key[p] & KEYMASK;
            unsigned w = k >> 5, b = k & 31;
            uint2 e = __ldg(&g_tab[w]);
            g_extra_rank[i] = e.y + __popc(e.x & ((1u << b) - 1u));
        }
    }
}

// ---------------------------------------------------------------------------
// Extras: red.add precomputed-rank rows onto owner-written rows.
// Last-finishing block resets pipeline state for the next graph replay.
__global__ void k_extras(const float4* __restrict__ feat,
                         float* __restrict__ out) {
    unsigned tot = g_extra_cnt * 8u;
    unsigned stride = EX_BLOCKS * 256;
    for (unsigned i = blockIdx.x * 256 + threadIdx.x; i < tot; i += stride) {
        unsigned idx = i >> 3;
        int lane = i & 7;
        unsigned p = __ldg(&g_extra[idx]);        // L2-hot (~120 KB)
        unsigned r = __ldg(&g_extra_rank[idx]);   // L2-hot
        float4 v = __ldg(&feat[(size_t)p * 8 + lane]);
        float* dst = out + (size_t)r * 32 + lane * 4;
        asm volatile("red.global.add.v4.f32 [%0], {%1,%2,%3,%4};"
                     :: "l"(dst), "f"(v.x), "f"(v.y), "f"(v.z), "f"(v.w)
                     : "memory");
    }
    __syncthreads();
    __shared__ unsigned s_last;
    if (threadIdx.x == 0) {
        __threadfence();
        s_last = (atomicAdd(&g_done, 1u) == (unsigned)(gridDim.x - 1));
    }
    __syncthreads();
    if (s_last) {
        if (threadIdx.x < SCAN_TILES / 2) {       // 256 threads x 2 descriptors
            g_desc[threadIdx.x * 2]     = 0ull;
            g_desc[threadIdx.x * 2 + 1] = 0ull;
        }
        if (threadIdx.x == 0) { g_extra_cnt = 0u; g_done = 0u; }
    }
}

// ---------------------------------------------------------------------------
extern "C" void kernel_launch(void* const* d_in, const int* in_sizes, int n_in,
                              void* d_out, int out_size) {
    const int4*   coords = (const int4*)d_in[0];    // [N,4] int32
    const float4* feat   = (const float4*)d_in[1];  // [N,32] f32
    float* out = (float*)d_out;
    int n  = in_sizes[0] / 4;
    int nb = (n + 255) / 256;

    k_setbits<<<(n / 2 + 255) / 256, 256>>>(coords, n);
    k_scan   <<<SCAN_TILES, SCAN_THREADS>>>();
    k_scatter<<<nb + PAD_BLOCKS + EXR_BLOCKS, 256>>>(feat, out, n, nb);
    k_extras <<<EX_BLOCKS, 256>>>(feat, out);
}